// round 2
// baseline (speedup 1.0000x reference)
#include <cuda_runtime.h>

#define NU   100000
#define NI   50000
#define NN   150000
#define EMB  64
#define NE   1500000
#define NDIR (2 * NE)
#define NB   4096

// ---------------- device scratch (static, no allocation) ----------------
__device__ int   g_deg[NN];
__device__ float g_dinv[NN];
__device__ int   g_rowptr[NN + 1];
__device__ int   g_cnt[NN];
__device__ int   g_col[NDIR];
__device__ float g_wgt[NDIR];
__device__ float g_rep1[NN * EMB];
__device__ float g_rep2[NN * EMB];
__device__ float g_rep3[NN * EMB];

// ---------------- small prep kernels ----------------
__global__ void zero_kernel() {
    int t = blockIdx.x * blockDim.x + threadIdx.x;
    if (t < NN) { g_deg[t] = 0; g_cnt[t] = 0; }
}

__global__ void hist_kernel(const int* __restrict__ eu, const int* __restrict__ ei) {
    int e = blockIdx.x * blockDim.x + threadIdx.x;
    if (e >= NE) return;
    atomicAdd(&g_deg[eu[e]], 1);
    atomicAdd(&g_deg[NU + ei[e]], 1);
}

__global__ void dinv_kernel() {
    int n = blockIdx.x * blockDim.x + threadIdx.x;
    if (n >= NN) return;
    int d = g_deg[n];
    g_dinv[n] = rsqrtf((float)(d > 0 ? d : 1));
}

// single-block exclusive scan over g_deg -> g_rowptr (150K elems, warp-shfl based)
__global__ void scan_kernel() {
    __shared__ int wsum[32];
    __shared__ int carry_s;
    int tid = threadIdx.x, lane = tid & 31, wid = tid >> 5;
    if (tid == 0) carry_s = 0;
    __syncthreads();
    for (int base = 0; base < NN; base += 1024) {
        int i = base + tid;
        int v = (i < NN) ? g_deg[i] : 0;
        int x = v;
        #pragma unroll
        for (int off = 1; off < 32; off <<= 1) {
            int t = __shfl_up_sync(0xffffffffu, x, off);
            if (lane >= off) x += t;
        }
        if (lane == 31) wsum[wid] = x;
        __syncthreads();
        if (wid == 0) {
            int y = wsum[lane];
            #pragma unroll
            for (int off = 1; off < 32; off <<= 1) {
                int t = __shfl_up_sync(0xffffffffu, y, off);
                if (lane >= off) y += t;
            }
            wsum[lane] = y;
        }
        __syncthreads();
        int warpoff = (wid == 0) ? 0 : wsum[wid - 1];
        int excl = carry_s + warpoff + x - v;
        if (i < NN) g_rowptr[i] = excl;
        __syncthreads();
        if (tid == 0) carry_s += wsum[31];
        __syncthreads();
    }
    if (tid == 0) g_rowptr[NN] = NDIR;
}

__global__ void fill_csr_kernel(const int* __restrict__ eu, const int* __restrict__ ei) {
    int e = blockIdx.x * blockDim.x + threadIdx.x;
    if (e >= NE) return;
    int u  = eu[e];
    int it = NU + ei[e];
    float w = g_dinv[u] * g_dinv[it];
    int p1 = g_rowptr[it] + atomicAdd(&g_cnt[it], 1);
    g_col[p1] = u;  g_wgt[p1] = w;
    int p2 = g_rowptr[u] + atomicAdd(&g_cnt[u], 1);
    g_col[p2] = it; g_wgt[p2] = w;
}

// ---------------- SpMM: one warp per dst row, pull-style, no float atomics ----
// mode: 0 = emb -> g_rep1 ; 1 = g_rep1 -> g_rep2 ; 2 = g_rep2 -> g_rep3
// Each lane handles a float2 (row = 64 floats = 32 lanes x float2 = one 256B req).
__global__ void __launch_bounds__(256) spmm_kernel(const float* __restrict__ emb, int mode) {
    int warp = (blockIdx.x * blockDim.x + threadIdx.x) >> 5;
    if (warp >= NN) return;
    int lane = threadIdx.x & 31;

    const float2* in  = (const float2*)((mode == 0) ? emb :
                        (mode == 1) ? g_rep1 : g_rep2);
    float2*       out = (float2*)((mode == 0) ? g_rep1 :
                        (mode == 1) ? g_rep2 : g_rep3);

    int beg = __ldg(&g_rowptr[warp]);
    int end = __ldg(&g_rowptr[warp + 1]);

    float sx = 0.f, sy = 0.f;
    int j = beg;
    // 4-way unrolled: 4 independent 256B row loads in flight
    for (; j + 4 <= end; j += 4) {
        int   c0 = __ldg(&g_col[j]);
        int   c1 = __ldg(&g_col[j + 1]);
        int   c2 = __ldg(&g_col[j + 2]);
        int   c3 = __ldg(&g_col[j + 3]);
        float w0 = __ldg(&g_wgt[j]);
        float w1 = __ldg(&g_wgt[j + 1]);
        float w2 = __ldg(&g_wgt[j + 2]);
        float w3 = __ldg(&g_wgt[j + 3]);
        float2 v0 = __ldg(&in[c0 * 32 + lane]);
        float2 v1 = __ldg(&in[c1 * 32 + lane]);
        float2 v2 = __ldg(&in[c2 * 32 + lane]);
        float2 v3 = __ldg(&in[c3 * 32 + lane]);
        sx += w0 * v0.x; sy += w0 * v0.y;
        sx += w1 * v1.x; sy += w1 * v1.y;
        sx += w2 * v2.x; sy += w2 * v2.y;
        sx += w3 * v3.x; sy += w3 * v3.y;
    }
    for (; j < end; j++) {
        int   c = __ldg(&g_col[j]);
        float w = __ldg(&g_wgt[j]);
        float2 v = __ldg(&in[c * 32 + lane]);
        sx += w * v.x; sy += w * v.y;
    }
    float2 r; r.x = sx; r.y = sy;
    out[warp * 32 + lane] = r;
}

// ---------------- fused epilogue: gather + mean over layers ----------------
// out[k][b][d] = 0.25 * (emb + r1 + r2 + r3)[node(k,b)][d]
__global__ void gather_final_kernel(const float* __restrict__ emb,
                                    const int* __restrict__ us,
                                    const int* __restrict__ pi,
                                    const int* __restrict__ ni,
                                    float* __restrict__ out) {
    int warp = (blockIdx.x * blockDim.x + threadIdx.x) >> 5;
    if (warp >= 3 * NB) return;
    int lane = threadIdx.x & 31;
    int k = warp / NB, b = warp - k * NB;
    int node = (k == 0) ? __ldg(&us[b])
             : (k == 1) ? (NU + __ldg(&pi[b]))
                        : (NU + __ldg(&ni[b]));
    long off = (long)node * 32 + lane;
    float2 e  = __ldg(&((const float2*)emb)[off]);
    float2 a1 = __ldg(&((const float2*)g_rep1)[off]);
    float2 a2 = __ldg(&((const float2*)g_rep2)[off]);
    float2 a3 = __ldg(&((const float2*)g_rep3)[off]);
    float2 r;
    r.x = 0.25f * (e.x + a1.x + a2.x + a3.x);
    r.y = 0.25f * (e.y + a1.y + a2.y + a3.y);
    ((float2*)out)[(long)warp * 32 + lane] = r;
}

// one warp per batch element: l2_norm_sq from raw embedding
__global__ void l2_kernel(const float* __restrict__ emb,
                          const int* __restrict__ us, const int* __restrict__ pi,
                          const int* __restrict__ ni, float* __restrict__ out) {
    int warp = (blockIdx.x * blockDim.x + threadIdx.x) >> 5;
    if (warp >= NB) return;
    int lane = threadIdx.x & 31;
    int n0 = __ldg(&us[warp]);
    int n1 = NU + __ldg(&pi[warp]);
    int n2 = NU + __ldg(&ni[warp]);
    const float2* e2 = (const float2*)emb;
    float s = 0.f;
    float2 a = __ldg(&e2[(long)n0 * 32 + lane]); s += a.x * a.x + a.y * a.y;
    float2 b = __ldg(&e2[(long)n1 * 32 + lane]); s += b.x * b.x + b.y * b.y;
    float2 c = __ldg(&e2[(long)n2 * 32 + lane]); s += c.x * c.x + c.y * c.y;
    #pragma unroll
    for (int off = 16; off; off >>= 1) s += __shfl_down_sync(0xffffffffu, s, off);
    if (lane == 0) out[3 * NB * EMB + warp] = s;
}

// ---------------- launch ----------------
extern "C" void kernel_launch(void* const* d_in, const int* in_sizes, int n_in,
                              void* d_out, int out_size) {
    const float* emb = (const float*)d_in[0];
    const int*   eu  = (const int*)d_in[1];
    const int*   ei  = (const int*)d_in[2];
    const int*   us  = (const int*)d_in[3];
    const int*   pi  = (const int*)d_in[4];
    const int*   ni  = (const int*)d_in[5];
    float*       out = (float*)d_out;

    const int T = 256;

    zero_kernel<<<(NN + T - 1) / T, T>>>();
    hist_kernel<<<(NE + T - 1) / T, T>>>(eu, ei);
    dinv_kernel<<<(NN + T - 1) / T, T>>>();
    scan_kernel<<<1, 1024>>>();
    fill_csr_kernel<<<(NE + T - 1) / T, T>>>(eu, ei);

    const int spmm_blocks = (NN * 32 + T - 1) / T;
    spmm_kernel<<<spmm_blocks, T>>>(emb, 0);   // emb  -> r1
    spmm_kernel<<<spmm_blocks, T>>>(emb, 1);   // r1   -> r2
    spmm_kernel<<<spmm_blocks, T>>>(emb, 2);   // r2   -> r3

    gather_final_kernel<<<(3 * NB * 32 + T - 1) / T, T>>>(emb, us, pi, ni, out);
    l2_kernel<<<(NB * 32 + T - 1) / T, T>>>(emb, us, pi, ni, out);
}

// round 7
// speedup vs baseline: 1.1142x; 1.1142x over previous
#include <cuda_runtime.h>

#define NU   100000
#define NI   50000
#define NN   150000
#define EMB  64
#define NE   1500000
#define NDIR (2 * NE)
#define NB   4096

#define SCAN_TILE   4096
#define SCAN_SHIFT  12
#define SCAN_BLOCKS ((NN + SCAN_TILE - 1) / SCAN_TILE)   // 37

// ---------------- device scratch (static, no allocation) ----------------
__device__ int   g_deg[NN];
__device__ float g_dinv[NN];
__device__ int   g_rowptr[NN + 1];     // tile-local exclusive prefixes
__device__ int   g_cnt[NN];
__device__ int   g_bsum[SCAN_BLOCKS];
__device__ int   g_boff[SCAN_BLOCKS];  // per-tile global offsets
__device__ int2  g_edge[NDIR];         // {col, __float_as_int(weight)}
__device__ float g_rep1[NN * EMB];
__device__ float g_rep2[NN * EMB];
__device__ float g_rep3[NN * EMB];

// final rowptr value = g_rowptr[x] + g_boff[x >> SCAN_SHIFT]
__device__ __forceinline__ int rowptr_at(int x) {
    return (x >= NN) ? NDIR : (__ldg(&g_rowptr[x]) + __ldg(&g_boff[x >> SCAN_SHIFT]));
}

// ---------------- small prep kernels ----------------
__global__ void zero_kernel() {
    int t = blockIdx.x * blockDim.x + threadIdx.x;
    if (t < NN) { g_deg[t] = 0; g_cnt[t] = 0; }
}

__global__ void hist_kernel(const int* __restrict__ eu, const int* __restrict__ ei) {
    int e = blockIdx.x * blockDim.x + threadIdx.x;
    if (e >= NE) return;
    atomicAdd(&g_deg[__ldg(&eu[e])], 1);
    atomicAdd(&g_deg[NU + __ldg(&ei[e])], 1);
}

// ---------------- hierarchical scan: deg -> rowptr (+ dinv folded in) -------
// Phase 1: per-block tile scan (4096 elems / block, 4 per thread).
__global__ void __launch_bounds__(1024) scan1_kernel() {
    __shared__ int wsum[32];
    int tid = threadIdx.x, lane = tid & 31, wid = tid >> 5;
    int i0 = blockIdx.x * SCAN_TILE + tid * 4;

    int v0 = (i0     < NN) ? g_deg[i0]     : 0;
    int v1 = (i0 + 1 < NN) ? g_deg[i0 + 1] : 0;
    int v2 = (i0 + 2 < NN) ? g_deg[i0 + 2] : 0;
    int v3 = (i0 + 3 < NN) ? g_deg[i0 + 3] : 0;
    int tsum = v0 + v1 + v2 + v3;

    // fold in dinv computation (same g_deg values, saves a kernel pass)
    if (i0     < NN) g_dinv[i0]     = rsqrtf((float)(v0 > 0 ? v0 : 1));
    if (i0 + 1 < NN) g_dinv[i0 + 1] = rsqrtf((float)(v1 > 0 ? v1 : 1));
    if (i0 + 2 < NN) g_dinv[i0 + 2] = rsqrtf((float)(v2 > 0 ? v2 : 1));
    if (i0 + 3 < NN) g_dinv[i0 + 3] = rsqrtf((float)(v3 > 0 ? v3 : 1));

    // inclusive scan of per-thread sums across the warp
    int x = tsum;
    #pragma unroll
    for (int off = 1; off < 32; off <<= 1) {
        int t = __shfl_up_sync(0xffffffffu, x, off);
        if (lane >= off) x += t;
    }
    if (lane == 31) wsum[wid] = x;
    __syncthreads();
    if (wid == 0) {
        int y = wsum[lane];
        #pragma unroll
        for (int off = 1; off < 32; off <<= 1) {
            int t = __shfl_up_sync(0xffffffffu, y, off);
            if (lane >= off) y += t;
        }
        wsum[lane] = y;
    }
    __syncthreads();
    int warpoff = (wid == 0) ? 0 : wsum[wid - 1];
    int run = warpoff + x - tsum;  // exclusive prefix of this thread within block

    if (i0     < NN) g_rowptr[i0]     = run;  run += v0;
    if (i0 + 1 < NN) g_rowptr[i0 + 1] = run;  run += v1;
    if (i0 + 2 < NN) g_rowptr[i0 + 2] = run;  run += v2;
    if (i0 + 3 < NN) g_rowptr[i0 + 3] = run;

    if (tid == 0) g_bsum[blockIdx.x] = wsum[31];  // block total
}

// Phase 2: exclusive scan of 37 block totals (trivial serial).
__global__ void scan2_kernel() {
    if (threadIdx.x == 0) {
        int run = 0;
        #pragma unroll 1
        for (int b = 0; b < SCAN_BLOCKS; b++) {
            g_boff[b] = run;
            run += g_bsum[b];
        }
    }
}

__global__ void fill_csr_kernel(const int* __restrict__ eu, const int* __restrict__ ei) {
    int e = blockIdx.x * blockDim.x + threadIdx.x;
    if (e >= NE) return;
    int u  = __ldg(&eu[e]);
    int it = NU + __ldg(&ei[e]);
    float w = __ldg(&g_dinv[u]) * __ldg(&g_dinv[it]);
    int wb = __float_as_int(w);
    int p1 = rowptr_at(it) + atomicAdd(&g_cnt[it], 1);
    g_edge[p1] = make_int2(u, wb);
    int p2 = rowptr_at(u) + atomicAdd(&g_cnt[u], 1);
    g_edge[p2] = make_int2(it, wb);
}

// ---------------- SpMM: one warp per dst row, pull-style, no float atomics ----
// mode: 0 = emb -> g_rep1 ; 1 = g_rep1 -> g_rep2 ; 2 = g_rep2 -> g_rep3
// Each lane handles a float2 (row = 64 floats = 32 lanes x float2 = one 256B req).
__global__ void __launch_bounds__(256) spmm_kernel(const float* __restrict__ emb, int mode) {
    int warp = (blockIdx.x * blockDim.x + threadIdx.x) >> 5;
    if (warp >= NN) return;
    int lane = threadIdx.x & 31;

    const float2* in  = (const float2*)((mode == 0) ? emb :
                        (mode == 1) ? g_rep1 : g_rep2);
    float2*       out = (float2*)((mode == 0) ? g_rep1 :
                        (mode == 1) ? g_rep2 : g_rep3);

    int beg = rowptr_at(warp);
    int end = rowptr_at(warp + 1);

    float sx = 0.f, sy = 0.f;
    int j = beg;
    // 4-way unrolled: 4 independent 256B row loads in flight
    for (; j + 4 <= end; j += 4) {
        int2 e0 = __ldg(&g_edge[j]);
        int2 e1 = __ldg(&g_edge[j + 1]);
        int2 e2 = __ldg(&g_edge[j + 2]);
        int2 e3 = __ldg(&g_edge[j + 3]);
        float2 v0 = __ldg(&in[e0.x * 32 + lane]);
        float2 v1 = __ldg(&in[e1.x * 32 + lane]);
        float2 v2 = __ldg(&in[e2.x * 32 + lane]);
        float2 v3 = __ldg(&in[e3.x * 32 + lane]);
        float w0 = __int_as_float(e0.y);
        float w1 = __int_as_float(e1.y);
        float w2 = __int_as_float(e2.y);
        float w3 = __int_as_float(e3.y);
        sx += w0 * v0.x; sy += w0 * v0.y;
        sx += w1 * v1.x; sy += w1 * v1.y;
        sx += w2 * v2.x; sy += w2 * v2.y;
        sx += w3 * v3.x; sy += w3 * v3.y;
    }
    for (; j < end; j++) {
        int2 e = __ldg(&g_edge[j]);
        float w = __int_as_float(e.y);
        float2 v = __ldg(&in[e.x * 32 + lane]);
        sx += w * v.x; sy += w * v.y;
    }
    float2 r; r.x = sx; r.y = sy;
    out[warp * 32 + lane] = r;
}

// ---------------- fused epilogue: gather + mean over layers ----------------
// out[k][b][d] = 0.25 * (emb + r1 + r2 + r3)[node(k,b)][d]
__global__ void gather_final_kernel(const float* __restrict__ emb,
                                    const int* __restrict__ us,
                                    const int* __restrict__ pi,
                                    const int* __restrict__ ni,
                                    float* __restrict__ out) {
    int warp = (blockIdx.x * blockDim.x + threadIdx.x) >> 5;
    if (warp >= 3 * NB) return;
    int lane = threadIdx.x & 31;
    int k = warp / NB, b = warp - k * NB;
    int node = (k == 0) ? __ldg(&us[b])
             : (k == 1) ? (NU + __ldg(&pi[b]))
                        : (NU + __ldg(&ni[b]));
    long off = (long)node * 32 + lane;
    float2 e  = __ldg(&((const float2*)emb)[off]);
    float2 a1 = __ldg(&((const float2*)g_rep1)[off]);
    float2 a2 = __ldg(&((const float2*)g_rep2)[off]);
    float2 a3 = __ldg(&((const float2*)g_rep3)[off]);
    float2 r;
    r.x = 0.25f * (e.x + a1.x + a2.x + a3.x);
    r.y = 0.25f * (e.y + a1.y + a2.y + a3.y);
    ((float2*)out)[(long)warp * 32 + lane] = r;
}

// one warp per batch element: l2_norm_sq from raw embedding
__global__ void l2_kernel(const float* __restrict__ emb,
                          const int* __restrict__ us, const int* __restrict__ pi,
                          const int* __restrict__ ni, float* __restrict__ out) {
    int warp = (blockIdx.x * blockDim.x + threadIdx.x) >> 5;
    if (warp >= NB) return;
    int lane = threadIdx.x & 31;
    int n0 = __ldg(&us[warp]);
    int n1 = NU + __ldg(&pi[warp]);
    int n2 = NU + __ldg(&ni[warp]);
    const float2* e2 = (const float2*)emb;
    float s = 0.f;
    float2 a = __ldg(&e2[(long)n0 * 32 + lane]); s += a.x * a.x + a.y * a.y;
    float2 b = __ldg(&e2[(long)n1 * 32 + lane]); s += b.x * b.x + b.y * b.y;
    float2 c = __ldg(&e2[(long)n2 * 32 + lane]); s += c.x * c.x + c.y * c.y;
    #pragma unroll
    for (int off = 16; off; off >>= 1) s += __shfl_down_sync(0xffffffffu, s, off);
    if (lane == 0) out[3 * NB * EMB + warp] = s;
}

// ---------------- launch ----------------
extern "C" void kernel_launch(void* const* d_in, const int* in_sizes, int n_in,
                              void* d_out, int out_size) {
    const float* emb = (const float*)d_in[0];
    const int*   eu  = (const int*)d_in[1];
    const int*   ei  = (const int*)d_in[2];
    const int*   us  = (const int*)d_in[3];
    const int*   pi  = (const int*)d_in[4];
    const int*   ni  = (const int*)d_in[5];
    float*       out = (float*)d_out;

    const int T = 256;

    zero_kernel<<<(NN + T - 1) / T, T>>>();
    hist_kernel<<<(NE + T - 1) / T, T>>>(eu, ei);

    scan1_kernel<<<SCAN_BLOCKS, 1024>>>();
    scan2_kernel<<<1, 32>>>();

    fill_csr_kernel<<<(NE + T - 1) / T, T>>>(eu, ei);

    const int spmm_blocks = (NN * 32 + T - 1) / T;
    spmm_kernel<<<spmm_blocks, T>>>(emb, 0);   // emb  -> r1
    spmm_kernel<<<spmm_blocks, T>>>(emb, 1);   // r1   -> r2
    spmm_kernel<<<spmm_blocks, T>>>(emb, 2);   // r2   -> r3

    gather_final_kernel<<<(3 * NB * 32 + T - 1) / T, T>>>(emb, us, pi, ni, out);
    l2_kernel<<<(NB * 32 + T - 1) / T, T>>>(emb, us, pi, ni, out);
}

// round 8
// speedup vs baseline: 1.4559x; 1.3067x over previous
#include <cuda_runtime.h>

#define NU   100000
#define NI   50000
#define NN   150000
#define EMB  64
#define NE   1500000
#define NDIR (2 * NE)
#define NB   4096

#define SCAN_TILE   4096
#define SCAN_SHIFT  12
#define SCAN_BLOCKS ((NN + SCAN_TILE - 1) / SCAN_TILE)   // 37

// ---------------- device scratch (static, no allocation) ----------------
__device__ int   g_deg[NN];
__device__ float g_dinv[NN];
__device__ int   g_rowptr[NN + 1];     // tile-local exclusive prefixes
__device__ int   g_cnt[NN];
__device__ int   g_bsum[SCAN_BLOCKS];
__device__ int   g_boff[SCAN_BLOCKS];  // per-tile global offsets
__device__ int2  g_edge[NDIR];         // {col, __float_as_int(weight)}
__device__ float g_rep1[NN * EMB];
__device__ float g_rep2[NN * EMB];

// final rowptr value = g_rowptr[x] + g_boff[x >> SCAN_SHIFT]
__device__ __forceinline__ int rowptr_at(int x) {
    return (x >= NN) ? NDIR : (__ldg(&g_rowptr[x]) + __ldg(&g_boff[x >> SCAN_SHIFT]));
}

// ---------------- small prep kernels ----------------
__global__ void zero_kernel() {
    int t = blockIdx.x * blockDim.x + threadIdx.x;
    if (t < NN) { g_deg[t] = 0; g_cnt[t] = 0; }
}

__global__ void hist_kernel(const int* __restrict__ eu, const int* __restrict__ ei) {
    int e = blockIdx.x * blockDim.x + threadIdx.x;
    if (e >= NE) return;
    atomicAdd(&g_deg[__ldg(&eu[e])], 1);
    atomicAdd(&g_deg[NU + __ldg(&ei[e])], 1);
}

// ---------------- hierarchical scan: deg -> rowptr (+ dinv folded in) -------
// Phase 1: per-block tile scan (4096 elems / block, 4 per thread).
__global__ void __launch_bounds__(1024) scan1_kernel() {
    __shared__ int wsum[32];
    int tid = threadIdx.x, lane = tid & 31, wid = tid >> 5;
    int i0 = blockIdx.x * SCAN_TILE + tid * 4;

    int v0 = (i0     < NN) ? g_deg[i0]     : 0;
    int v1 = (i0 + 1 < NN) ? g_deg[i0 + 1] : 0;
    int v2 = (i0 + 2 < NN) ? g_deg[i0 + 2] : 0;
    int v3 = (i0 + 3 < NN) ? g_deg[i0 + 3] : 0;
    int tsum = v0 + v1 + v2 + v3;

    // fold in dinv computation (same g_deg values, saves a kernel pass)
    if (i0     < NN) g_dinv[i0]     = rsqrtf((float)(v0 > 0 ? v0 : 1));
    if (i0 + 1 < NN) g_dinv[i0 + 1] = rsqrtf((float)(v1 > 0 ? v1 : 1));
    if (i0 + 2 < NN) g_dinv[i0 + 2] = rsqrtf((float)(v2 > 0 ? v2 : 1));
    if (i0 + 3 < NN) g_dinv[i0 + 3] = rsqrtf((float)(v3 > 0 ? v3 : 1));

    // inclusive scan of per-thread sums across the warp
    int x = tsum;
    #pragma unroll
    for (int off = 1; off < 32; off <<= 1) {
        int t = __shfl_up_sync(0xffffffffu, x, off);
        if (lane >= off) x += t;
    }
    if (lane == 31) wsum[wid] = x;
    __syncthreads();
    if (wid == 0) {
        int y = wsum[lane];
        #pragma unroll
        for (int off = 1; off < 32; off <<= 1) {
            int t = __shfl_up_sync(0xffffffffu, y, off);
            if (lane >= off) y += t;
        }
        wsum[lane] = y;
    }
    __syncthreads();
    int warpoff = (wid == 0) ? 0 : wsum[wid - 1];
    int run = warpoff + x - tsum;  // exclusive prefix of this thread within block

    if (i0     < NN) g_rowptr[i0]     = run;  run += v0;
    if (i0 + 1 < NN) g_rowptr[i0 + 1] = run;  run += v1;
    if (i0 + 2 < NN) g_rowptr[i0 + 2] = run;  run += v2;
    if (i0 + 3 < NN) g_rowptr[i0 + 3] = run;

    if (tid == 0) g_bsum[blockIdx.x] = wsum[31];  // block total
}

// Phase 2: exclusive scan of 37 block totals (trivial serial).
__global__ void scan2_kernel() {
    if (threadIdx.x == 0) {
        int run = 0;
        #pragma unroll 1
        for (int b = 0; b < SCAN_BLOCKS; b++) {
            g_boff[b] = run;
            run += g_bsum[b];
        }
    }
}

__global__ void fill_csr_kernel(const int* __restrict__ eu, const int* __restrict__ ei) {
    int e = blockIdx.x * blockDim.x + threadIdx.x;
    if (e >= NE) return;
    int u  = __ldg(&eu[e]);
    int it = NU + __ldg(&ei[e]);
    float w = __ldg(&g_dinv[u]) * __ldg(&g_dinv[it]);
    int wb = __float_as_int(w);
    int p1 = rowptr_at(it) + atomicAdd(&g_cnt[it], 1);
    g_edge[p1] = make_int2(u, wb);
    int p2 = rowptr_at(u) + atomicAdd(&g_cnt[u], 1);
    g_edge[p2] = make_int2(it, wb);
}

// ---------------- SpMM: one warp per dst row, pull-style, no float atomics ----
// mode: 0 = emb -> g_rep1 ; 1 = g_rep1 -> g_rep2
// Each lane handles a float2 (row = 64 floats = 32 lanes x float2 = one 256B req).
__global__ void __launch_bounds__(256) spmm_kernel(const float* __restrict__ emb, int mode) {
    int warp = (blockIdx.x * blockDim.x + threadIdx.x) >> 5;
    if (warp >= NN) return;
    int lane = threadIdx.x & 31;

    const float2* in  = (const float2*)((mode == 0) ? emb : g_rep1);
    float2*       out = (float2*)((mode == 0) ? g_rep1 : g_rep2);

    int beg = rowptr_at(warp);
    int end = rowptr_at(warp + 1);

    float sx = 0.f, sy = 0.f;
    int j = beg;
    // 4-way unrolled: 4 independent 256B row loads in flight
    for (; j + 4 <= end; j += 4) {
        int2 e0 = __ldg(&g_edge[j]);
        int2 e1 = __ldg(&g_edge[j + 1]);
        int2 e2 = __ldg(&g_edge[j + 2]);
        int2 e3 = __ldg(&g_edge[j + 3]);
        float2 v0 = __ldg(&in[e0.x * 32 + lane]);
        float2 v1 = __ldg(&in[e1.x * 32 + lane]);
        float2 v2 = __ldg(&in[e2.x * 32 + lane]);
        float2 v3 = __ldg(&in[e3.x * 32 + lane]);
        float w0 = __int_as_float(e0.y);
        float w1 = __int_as_float(e1.y);
        float w2 = __int_as_float(e2.y);
        float w3 = __int_as_float(e3.y);
        sx += w0 * v0.x; sy += w0 * v0.y;
        sx += w1 * v1.x; sy += w1 * v1.y;
        sx += w2 * v2.x; sy += w2 * v2.y;
        sx += w3 * v3.x; sy += w3 * v3.y;
    }
    for (; j < end; j++) {
        int2 e = __ldg(&g_edge[j]);
        float w = __int_as_float(e.y);
        float2 v = __ldg(&in[e.x * 32 + lane]);
        sx += w * v.x; sy += w * v.y;
    }
    float2 r; r.x = sx; r.y = sy;
    out[warp * 32 + lane] = r;
}

// ---------------- fused epilogue: layer-3 on the fly + mean over layers ------
// out[k][b][d] = 0.25 * (emb[n] + r1[n] + r2[n] + (A@r2)[n])[d]
// Layer 3 is only needed at the 3*NB batch rows, so compute it here per-row
// (~307K edge gathers) instead of a full 3M-edge SpMM pass.
__global__ void __launch_bounds__(256) gather_final_kernel(
        const float* __restrict__ emb,
        const int* __restrict__ us,
        const int* __restrict__ pi,
        const int* __restrict__ ni,
        float* __restrict__ out) {
    int warp = (blockIdx.x * blockDim.x + threadIdx.x) >> 5;
    if (warp >= 3 * NB) return;
    int lane = threadIdx.x & 31;
    int k = warp / NB, b = warp - k * NB;
    int node = (k == 0) ? __ldg(&us[b])
             : (k == 1) ? (NU + __ldg(&pi[b]))
                        : (NU + __ldg(&ni[b]));
    long off = (long)node * 32 + lane;
    float2 e  = __ldg(&((const float2*)emb)[off]);
    float2 a1 = __ldg(&((const float2*)g_rep1)[off]);
    float2 a2 = __ldg(&((const float2*)g_rep2)[off]);
    float sx = e.x + a1.x + a2.x;
    float sy = e.y + a1.y + a2.y;

    // layer-3 term: sum_j w_j * r2[col_j]
    const float2* in = (const float2*)g_rep2;
    int beg = rowptr_at(node);
    int end = rowptr_at(node + 1);
    int j = beg;
    for (; j + 4 <= end; j += 4) {
        int2 e0 = __ldg(&g_edge[j]);
        int2 e1 = __ldg(&g_edge[j + 1]);
        int2 e2 = __ldg(&g_edge[j + 2]);
        int2 e3 = __ldg(&g_edge[j + 3]);
        float2 v0 = __ldg(&in[e0.x * 32 + lane]);
        float2 v1 = __ldg(&in[e1.x * 32 + lane]);
        float2 v2 = __ldg(&in[e2.x * 32 + lane]);
        float2 v3 = __ldg(&in[e3.x * 32 + lane]);
        sx += __int_as_float(e0.y) * v0.x; sy += __int_as_float(e0.y) * v0.y;
        sx += __int_as_float(e1.y) * v1.x; sy += __int_as_float(e1.y) * v1.y;
        sx += __int_as_float(e2.y) * v2.x; sy += __int_as_float(e2.y) * v2.y;
        sx += __int_as_float(e3.y) * v3.x; sy += __int_as_float(e3.y) * v3.y;
    }
    for (; j < end; j++) {
        int2 ed = __ldg(&g_edge[j]);
        float w = __int_as_float(ed.y);
        float2 v = __ldg(&in[ed.x * 32 + lane]);
        sx += w * v.x; sy += w * v.y;
    }

    float2 r;
    r.x = 0.25f * sx;
    r.y = 0.25f * sy;
    ((float2*)out)[(long)warp * 32 + lane] = r;
}

// one warp per batch element: l2_norm_sq from raw embedding
__global__ void l2_kernel(const float* __restrict__ emb,
                          const int* __restrict__ us, const int* __restrict__ pi,
                          const int* __restrict__ ni, float* __restrict__ out) {
    int warp = (blockIdx.x * blockDim.x + threadIdx.x) >> 5;
    if (warp >= NB) return;
    int lane = threadIdx.x & 31;
    int n0 = __ldg(&us[warp]);
    int n1 = NU + __ldg(&pi[warp]);
    int n2 = NU + __ldg(&ni[warp]);
    const float2* e2 = (const float2*)emb;
    float s = 0.f;
    float2 a = __ldg(&e2[(long)n0 * 32 + lane]); s += a.x * a.x + a.y * a.y;
    float2 b = __ldg(&e2[(long)n1 * 32 + lane]); s += b.x * b.x + b.y * b.y;
    float2 c = __ldg(&e2[(long)n2 * 32 + lane]); s += c.x * c.x + c.y * c.y;
    #pragma unroll
    for (int off = 16; off; off >>= 1) s += __shfl_down_sync(0xffffffffu, s, off);
    if (lane == 0) out[3 * NB * EMB + warp] = s;
}

// ---------------- launch ----------------
extern "C" void kernel_launch(void* const* d_in, const int* in_sizes, int n_in,
                              void* d_out, int out_size) {
    const float* emb = (const float*)d_in[0];
    const int*   eu  = (const int*)d_in[1];
    const int*   ei  = (const int*)d_in[2];
    const int*   us  = (const int*)d_in[3];
    const int*   pi  = (const int*)d_in[4];
    const int*   ni  = (const int*)d_in[5];
    float*       out = (float*)d_out;

    const int T = 256;

    zero_kernel<<<(NN + T - 1) / T, T>>>();
    hist_kernel<<<(NE + T - 1) / T, T>>>(eu, ei);

    scan1_kernel<<<SCAN_BLOCKS, 1024>>>();
    scan2_kernel<<<1, 32>>>();

    fill_csr_kernel<<<(NE + T - 1) / T, T>>>(eu, ei);

    const int spmm_blocks = (NN * 32 + T - 1) / T;
    spmm_kernel<<<spmm_blocks, T>>>(emb, 0);   // emb  -> r1
    spmm_kernel<<<spmm_blocks, T>>>(emb, 1);   // r1   -> r2

    gather_final_kernel<<<(3 * NB * 32 + T - 1) / T, T>>>(emb, us, pi, ni, out);
    l2_kernel<<<(NB * 32 + T - 1) / T, T>>>(emb, us, pi, ni, out);
}

// round 9
// speedup vs baseline: 1.7329x; 1.1902x over previous
#include <cuda_runtime.h>
#include <cuda_fp16.h>

#define NU   100000
#define NI   50000
#define NN   150000
#define EMB  64
#define NE   1500000
#define NDIR (2 * NE)
#define NB   4096

#define SCAN_TILE   4096
#define SCAN_SHIFT  12
#define SCAN_BLOCKS ((NN + SCAN_TILE - 1) / SCAN_TILE)   // 37

// ---------------- device scratch (static, no allocation) ----------------
__device__ int     g_deg[NN];
__device__ float   g_dinv[NN];
__device__ int     g_rowptr[NN + 1];   // tile-local exclusive prefixes
__device__ int     g_cnt[NN];
__device__ int     g_bsum[SCAN_BLOCKS];
__device__ int     g_boff[SCAN_BLOCKS];
__device__ int2    g_edge[NDIR];       // {col, __float_as_int(weight)}
__device__ __half2 g_rep1[NN * EMB / 2];   // fp16 storage, fp32 accumulation
__device__ __half2 g_rep2[NN * EMB / 2];

// final rowptr value = g_rowptr[x] + g_boff[x >> SCAN_SHIFT]
__device__ __forceinline__ int rowptr_at(int x) {
    return (x >= NN) ? NDIR : (__ldg(&g_rowptr[x]) + __ldg(&g_boff[x >> SCAN_SHIFT]));
}

// ---------------- small prep kernels ----------------
__global__ void zero_kernel() {
    int t = blockIdx.x * blockDim.x + threadIdx.x;
    if (t < NN) { g_deg[t] = 0; g_cnt[t] = 0; }
}

__global__ void hist_kernel(const int* __restrict__ eu, const int* __restrict__ ei) {
    int e = blockIdx.x * blockDim.x + threadIdx.x;
    if (e >= NE) return;
    atomicAdd(&g_deg[__ldg(&eu[e])], 1);
    atomicAdd(&g_deg[NU + __ldg(&ei[e])], 1);
}

// ---------------- hierarchical scan: deg -> rowptr (+ dinv folded in) -------
__global__ void __launch_bounds__(1024) scan1_kernel() {
    __shared__ int wsum[32];
    int tid = threadIdx.x, lane = tid & 31, wid = tid >> 5;
    int i0 = blockIdx.x * SCAN_TILE + tid * 4;

    int v0 = (i0     < NN) ? g_deg[i0]     : 0;
    int v1 = (i0 + 1 < NN) ? g_deg[i0 + 1] : 0;
    int v2 = (i0 + 2 < NN) ? g_deg[i0 + 2] : 0;
    int v3 = (i0 + 3 < NN) ? g_deg[i0 + 3] : 0;
    int tsum = v0 + v1 + v2 + v3;

    if (i0     < NN) g_dinv[i0]     = rsqrtf((float)(v0 > 0 ? v0 : 1));
    if (i0 + 1 < NN) g_dinv[i0 + 1] = rsqrtf((float)(v1 > 0 ? v1 : 1));
    if (i0 + 2 < NN) g_dinv[i0 + 2] = rsqrtf((float)(v2 > 0 ? v2 : 1));
    if (i0 + 3 < NN) g_dinv[i0 + 3] = rsqrtf((float)(v3 > 0 ? v3 : 1));

    int x = tsum;
    #pragma unroll
    for (int off = 1; off < 32; off <<= 1) {
        int t = __shfl_up_sync(0xffffffffu, x, off);
        if (lane >= off) x += t;
    }
    if (lane == 31) wsum[wid] = x;
    __syncthreads();
    if (wid == 0) {
        int y = wsum[lane];
        #pragma unroll
        for (int off = 1; off < 32; off <<= 1) {
            int t = __shfl_up_sync(0xffffffffu, y, off);
            if (lane >= off) y += t;
        }
        wsum[lane] = y;
    }
    __syncthreads();
    int warpoff = (wid == 0) ? 0 : wsum[wid - 1];
    int run = warpoff + x - tsum;

    if (i0     < NN) g_rowptr[i0]     = run;  run += v0;
    if (i0 + 1 < NN) g_rowptr[i0 + 1] = run;  run += v1;
    if (i0 + 2 < NN) g_rowptr[i0 + 2] = run;  run += v2;
    if (i0 + 3 < NN) g_rowptr[i0 + 3] = run;

    if (tid == 0) g_bsum[blockIdx.x] = wsum[31];
}

__global__ void scan2_kernel() {
    if (threadIdx.x == 0) {
        int run = 0;
        #pragma unroll 1
        for (int b = 0; b < SCAN_BLOCKS; b++) {
            g_boff[b] = run;
            run += g_bsum[b];
        }
    }
}

__global__ void fill_csr_kernel(const int* __restrict__ eu, const int* __restrict__ ei) {
    int e = blockIdx.x * blockDim.x + threadIdx.x;
    if (e >= NE) return;
    int u  = __ldg(&eu[e]);
    int it = NU + __ldg(&ei[e]);
    float w = __ldg(&g_dinv[u]) * __ldg(&g_dinv[it]);
    int wb = __float_as_int(w);
    int p1 = rowptr_at(it) + atomicAdd(&g_cnt[it], 1);
    g_edge[p1] = make_int2(u, wb);
    int p2 = rowptr_at(u) + atomicAdd(&g_cnt[u], 1);
    g_edge[p2] = make_int2(it, wb);
}

// ---------------- SpMM layer 1: emb (f32) -> rep1 (f16) ---------------------
__global__ void __launch_bounds__(256) spmm1_kernel(const float* __restrict__ emb) {
    int warp = (blockIdx.x * blockDim.x + threadIdx.x) >> 5;
    if (warp >= NN) return;
    int lane = threadIdx.x & 31;
    const float2* in = (const float2*)emb;

    int beg = rowptr_at(warp);
    int end = rowptr_at(warp + 1);

    float sx = 0.f, sy = 0.f;
    int j = beg;
    for (; j + 4 <= end; j += 4) {
        int2 e0 = __ldg(&g_edge[j]);
        int2 e1 = __ldg(&g_edge[j + 1]);
        int2 e2 = __ldg(&g_edge[j + 2]);
        int2 e3 = __ldg(&g_edge[j + 3]);
        float2 v0 = __ldg(&in[e0.x * 32 + lane]);
        float2 v1 = __ldg(&in[e1.x * 32 + lane]);
        float2 v2 = __ldg(&in[e2.x * 32 + lane]);
        float2 v3 = __ldg(&in[e3.x * 32 + lane]);
        float w0 = __int_as_float(e0.y), w1 = __int_as_float(e1.y);
        float w2 = __int_as_float(e2.y), w3 = __int_as_float(e3.y);
        sx += w0 * v0.x; sy += w0 * v0.y;
        sx += w1 * v1.x; sy += w1 * v1.y;
        sx += w2 * v2.x; sy += w2 * v2.y;
        sx += w3 * v3.x; sy += w3 * v3.y;
    }
    for (; j < end; j++) {
        int2 e = __ldg(&g_edge[j]);
        float w = __int_as_float(e.y);
        float2 v = __ldg(&in[e.x * 32 + lane]);
        sx += w * v.x; sy += w * v.y;
    }
    g_rep1[warp * 32 + lane] = __float22half2_rn(make_float2(sx, sy));
}

// ---------------- SpMM layer 2: rep1 (f16) -> rep2 (f16) --------------------
__global__ void __launch_bounds__(256) spmm2_kernel() {
    int warp = (blockIdx.x * blockDim.x + threadIdx.x) >> 5;
    if (warp >= NN) return;
    int lane = threadIdx.x & 31;

    int beg = rowptr_at(warp);
    int end = rowptr_at(warp + 1);

    float sx = 0.f, sy = 0.f;
    int j = beg;
    for (; j + 4 <= end; j += 4) {
        int2 e0 = __ldg(&g_edge[j]);
        int2 e1 = __ldg(&g_edge[j + 1]);
        int2 e2 = __ldg(&g_edge[j + 2]);
        int2 e3 = __ldg(&g_edge[j + 3]);
        float2 v0 = __half22float2(__ldg(&g_rep1[e0.x * 32 + lane]));
        float2 v1 = __half22float2(__ldg(&g_rep1[e1.x * 32 + lane]));
        float2 v2 = __half22float2(__ldg(&g_rep1[e2.x * 32 + lane]));
        float2 v3 = __half22float2(__ldg(&g_rep1[e3.x * 32 + lane]));
        float w0 = __int_as_float(e0.y), w1 = __int_as_float(e1.y);
        float w2 = __int_as_float(e2.y), w3 = __int_as_float(e3.y);
        sx += w0 * v0.x; sy += w0 * v0.y;
        sx += w1 * v1.x; sy += w1 * v1.y;
        sx += w2 * v2.x; sy += w2 * v2.y;
        sx += w3 * v3.x; sy += w3 * v3.y;
    }
    for (; j < end; j++) {
        int2 e = __ldg(&g_edge[j]);
        float w = __int_as_float(e.y);
        float2 v = __half22float2(__ldg(&g_rep1[e.x * 32 + lane]));
        sx += w * v.x; sy += w * v.y;
    }
    g_rep2[warp * 32 + lane] = __float22half2_rn(make_float2(sx, sy));
}

// ---------------- fused epilogue: layer-3 on the fly + mean over layers ------
// out[k][b][d] = 0.25 * (emb[n] + r1[n] + r2[n] + (A@r2)[n])[d]
__global__ void __launch_bounds__(256) gather_final_kernel(
        const float* __restrict__ emb,
        const int* __restrict__ us,
        const int* __restrict__ pi,
        const int* __restrict__ ni,
        float* __restrict__ out) {
    int warp = (blockIdx.x * blockDim.x + threadIdx.x) >> 5;
    if (warp >= 3 * NB) return;
    int lane = threadIdx.x & 31;
    int k = warp / NB, b = warp - k * NB;
    int node = (k == 0) ? __ldg(&us[b])
             : (k == 1) ? (NU + __ldg(&pi[b]))
                        : (NU + __ldg(&ni[b]));
    long off = (long)node * 32 + lane;
    float2 e  = __ldg(&((const float2*)emb)[off]);
    float2 a1 = __half22float2(__ldg(&g_rep1[off]));
    float2 a2 = __half22float2(__ldg(&g_rep2[off]));
    float sx = e.x + a1.x + a2.x;
    float sy = e.y + a1.y + a2.y;

    // layer-3 term: sum_j w_j * r2[col_j]
    int beg = rowptr_at(node);
    int end = rowptr_at(node + 1);
    int j = beg;
    for (; j + 4 <= end; j += 4) {
        int2 e0 = __ldg(&g_edge[j]);
        int2 e1 = __ldg(&g_edge[j + 1]);
        int2 e2 = __ldg(&g_edge[j + 2]);
        int2 e3 = __ldg(&g_edge[j + 3]);
        float2 v0 = __half22float2(__ldg(&g_rep2[e0.x * 32 + lane]));
        float2 v1 = __half22float2(__ldg(&g_rep2[e1.x * 32 + lane]));
        float2 v2 = __half22float2(__ldg(&g_rep2[e2.x * 32 + lane]));
        float2 v3 = __half22float2(__ldg(&g_rep2[e3.x * 32 + lane]));
        sx += __int_as_float(e0.y) * v0.x; sy += __int_as_float(e0.y) * v0.y;
        sx += __int_as_float(e1.y) * v1.x; sy += __int_as_float(e1.y) * v1.y;
        sx += __int_as_float(e2.y) * v2.x; sy += __int_as_float(e2.y) * v2.y;
        sx += __int_as_float(e3.y) * v3.x; sy += __int_as_float(e3.y) * v3.y;
    }
    for (; j < end; j++) {
        int2 ed = __ldg(&g_edge[j]);
        float w = __int_as_float(ed.y);
        float2 v = __half22float2(__ldg(&g_rep2[ed.x * 32 + lane]));
        sx += w * v.x; sy += w * v.y;
    }

    float2 r;
    r.x = 0.25f * sx;
    r.y = 0.25f * sy;
    ((float2*)out)[(long)warp * 32 + lane] = r;
}

// one warp per batch element: l2_norm_sq from raw embedding
__global__ void l2_kernel(const float* __restrict__ emb,
                          const int* __restrict__ us, const int* __restrict__ pi,
                          const int* __restrict__ ni, float* __restrict__ out) {
    int warp = (blockIdx.x * blockDim.x + threadIdx.x) >> 5;
    if (warp >= NB) return;
    int lane = threadIdx.x & 31;
    int n0 = __ldg(&us[warp]);
    int n1 = NU + __ldg(&pi[warp]);
    int n2 = NU + __ldg(&ni[warp]);
    const float2* e2 = (const float2*)emb;
    float s = 0.f;
    float2 a = __ldg(&e2[(long)n0 * 32 + lane]); s += a.x * a.x + a.y * a.y;
    float2 b = __ldg(&e2[(long)n1 * 32 + lane]); s += b.x * b.x + b.y * b.y;
    float2 c = __ldg(&e2[(long)n2 * 32 + lane]); s += c.x * c.x + c.y * c.y;
    #pragma unroll
    for (int off = 16; off; off >>= 1) s += __shfl_down_sync(0xffffffffu, s, off);
    if (lane == 0) out[3 * NB * EMB + warp] = s;
}

// ---------------- launch ----------------
extern "C" void kernel_launch(void* const* d_in, const int* in_sizes, int n_in,
                              void* d_out, int out_size) {
    const float* emb = (const float*)d_in[0];
    const int*   eu  = (const int*)d_in[1];
    const int*   ei  = (const int*)d_in[2];
    const int*   us  = (const int*)d_in[3];
    const int*   pi  = (const int*)d_in[4];
    const int*   ni  = (const int*)d_in[5];
    float*       out = (float*)d_out;

    const int T = 256;

    zero_kernel<<<(NN + T - 1) / T, T>>>();
    hist_kernel<<<(NE + T - 1) / T, T>>>(eu, ei);

    scan1_kernel<<<SCAN_BLOCKS, 1024>>>();
    scan2_kernel<<<1, 32>>>();

    fill_csr_kernel<<<(NE + T - 1) / T, T>>>(eu, ei);

    const int spmm_blocks = (NN * 32 + T - 1) / T;
    spmm1_kernel<<<spmm_blocks, T>>>(emb);   // emb -> r1 (f16)
    spmm2_kernel<<<spmm_blocks, T>>>();      // r1  -> r2 (f16)

    gather_final_kernel<<<(3 * NB * 32 + T - 1) / T, T>>>(emb, us, pi, ni, out);
    l2_kernel<<<(NB * 32 + T - 1) / T, T>>>(emb, us, pi, ni, out);
}